// round 8
// baseline (speedup 1.0000x reference)
#include <cuda_runtime.h>
#include <stdint.h>

#define N_NODES 50000
#define N_EDGES 600000
#define IN_DIM  16
#define HID     128
#define OUT_DIM 4
#define NT_GEMM ((N_NODES + 63) / 64)   // 782 row-tiles of 64
#define NB      ((N_NODES + 255) / 256) // 196 scan chunks

// ---------------- device scratch (no runtime allocation allowed) ----------------
__device__ int   g_deg[N_NODES];     // zero at start (static init + self-clean in k_layer1)
__device__ int   g_cur[N_NODES];     // zeroed in k_offsets_all each call
__device__ int   g_off[N_NODES + 1];
__device__ int   g_esrc[N_EDGES];
__device__ float g_invdeg[N_NODES];
__device__ float g_hA[N_NODES * HID];
__device__ float g_hB[N_NODES * HID];
__device__ int   g_is64;

// ---------------- f32x2 helpers (Blackwell packed fp32) ----------------
typedef unsigned long long ull;

__device__ __forceinline__ ull packf2(float x, float y) {
    ull r; asm("mov.b64 %0, {%1, %2};" : "=l"(r) : "f"(x), "f"(y)); return r;
}
__device__ __forceinline__ void ffma2(ull& d, ull a, ull b) {
    asm("fma.rn.f32x2 %0, %1, %2, %0;" : "+l"(d) : "l"(a), "l"(b));
}
__device__ __forceinline__ float2 unpackf2(ull v) {
    float2 r; asm("mov.b64 {%0, %1}, %2;" : "=f"(r.x), "=f"(r.y) : "l"(v)); return r;
}

// ---------------- dtype detection for edge_index (int64 vs int32) ----------------
__global__ void k_detect(const unsigned int* __restrict__ ei32) {
    if (threadIdx.x == 0) {
        unsigned int acc = 0;
        #pragma unroll
        for (int i = 0; i < 64; i++) acc |= ei32[2 * i + 1];
        g_is64 = (acc == 0) ? 1 : 0;
    }
}

__device__ __forceinline__ int load_edge(const void* ei, int idx, int is64) {
    if (is64) return (int)((const long long*)ei)[idx];
    return ((const int*)ei)[idx];
}

// ---------------- CSR build ----------------
__global__ void k_count(const void* __restrict__ ei) {
    int e = blockIdx.x * blockDim.x + threadIdx.x;
    if (e >= N_EDGES) return;
    int is64 = g_is64;
    int d = load_edge(ei, N_EDGES + e, is64);
    if ((unsigned)d < (unsigned)N_NODES)
        atomicAdd(&g_deg[d], 1);
}

// Single-kernel scan: every block (196 x 256) redundantly computes all chunk
// sums + their prefix, then scans its own 256-element chunk. Also writes
// invdeg and zeroes g_cur for the subsequent k_fill.
__global__ void k_offsets_all() {
    __shared__ int cs[256];     // original chunk sums
    __shared__ int inc[256];    // inclusive scan of chunk sums
    __shared__ int ws[8];
    int t = threadIdx.x, lane = t & 31, w = t >> 5;

    // phase A: chunk sums (thread t sums deg[256t .. 256t+256))
    int s = 0;
    if (t < NB) {
        const int* p = g_deg + t * 256;
        int lim = N_NODES - t * 256; if (lim > 256) lim = 256;
        for (int j = 0; j < lim; j++) s += p[j];
    }
    cs[t] = s;
    __syncthreads();

    // phase B: inclusive scan of the 256 chunk sums
    {
        int x = cs[t];
        #pragma unroll
        for (int d = 1; d < 32; d <<= 1) {
            int y = __shfl_up_sync(0xffffffffu, x, d);
            if (lane >= d) x += y;
        }
        if (lane == 31) ws[w] = x;
        __syncthreads();
        if (t < 8) {
            int sv = ws[t], xs = sv;
            #pragma unroll
            for (int d = 1; d < 8; d <<= 1) {
                int y = __shfl_up_sync(0x000000ffu, xs, d);
                if (t >= d) xs += y;
            }
            ws[t] = xs - sv;   // exclusive prefix of warp totals
        }
        __syncthreads();
        inc[t] = ws[w] + x;
        __syncthreads();
    }
    int base  = inc[blockIdx.x] - cs[blockIdx.x];
    int total = inc[255];
    __syncthreads();   // ws reused below

    // phase C: local scan of own chunk
    int i = blockIdx.x * 256 + t;
    int v = (i < N_NODES) ? g_deg[i] : 0;
    int x = v;
    #pragma unroll
    for (int d = 1; d < 32; d <<= 1) {
        int y = __shfl_up_sync(0xffffffffu, x, d);
        if (lane >= d) x += y;
    }
    if (lane == 31) ws[w] = x;
    __syncthreads();
    if (t < 8) {
        int sv = ws[t], xs = sv;
        #pragma unroll
        for (int d = 1; d < 8; d <<= 1) {
            int y = __shfl_up_sync(0x000000ffu, xs, d);
            if (t >= d) xs += y;
        }
        ws[t] = xs - sv;
    }
    __syncthreads();
    if (i < N_NODES) {
        g_off[i]    = base + ws[w] + (x - v);
        g_invdeg[i] = 1.0f / (float)(v > 0 ? v : 1);
        g_cur[i]    = 0;                     // ready for k_fill
    }
    if (blockIdx.x == NB - 1 && t == 0) g_off[N_NODES] = total;
}

__global__ void k_fill(const void* __restrict__ ei) {
    int e = blockIdx.x * blockDim.x + threadIdx.x;
    if (e >= N_EDGES) return;
    int is64 = g_is64;
    int d = load_edge(ei, N_EDGES + e, is64);
    if ((unsigned)d >= (unsigned)N_NODES) return;
    int s = load_edge(ei, e, is64);
    if ((unsigned)s >= (unsigned)N_NODES) s = 0;
    int p = g_off[d] + atomicAdd(&g_cur[d], 1);
    if ((unsigned)p < (unsigned)N_EDGES)
        g_esrc[p] = s;
}

// ---------------- layer 1: aggregate x (16-d) + dual GEMM 16->128 + relu ----
// Also self-cleans g_deg for the next graph replay.
__global__ void k_layer1(const float* __restrict__ x,
                         const float* __restrict__ Wl,
                         const float* __restrict__ Wr,
                         const float* __restrict__ b,
                         float* __restrict__ hout) {
    for (int i = blockIdx.x * blockDim.x + threadIdx.x; i < N_NODES;
         i += gridDim.x * blockDim.x)
        g_deg[i] = 0;

    __shared__ float sWl[IN_DIM * HID], sWr[IN_DIM * HID], sb[HID];
    __shared__ float red[128], sagg[IN_DIM], sx[IN_DIM];
    int t = threadIdx.x;
    for (int i = t; i < HID * IN_DIM; i += 128) {
        int o = i >> 4, k = i & 15;
        sWl[k * HID + o] = Wl[i];   // sW[k][o] = W[o][k]
        sWr[k * HID + o] = Wr[i];
    }
    sb[t] = b[t];
    __syncthreads();
    int k = t & 15, s = t >> 4;
    for (int n = blockIdx.x; n < N_NODES; n += gridDim.x) {
        int e0 = g_off[n], e1 = g_off[n + 1];
        float p = 0.f;
        for (int e = e0 + s; e < e1; e += 8)
            p += x[g_esrc[e] * IN_DIM + k];
        red[t] = p;
        __syncthreads();
        if (t < 16) {
            float a = 0.f;
            #pragma unroll
            for (int j = 0; j < 8; j++) a += red[j * 16 + t];
            sagg[t] = a * g_invdeg[n];
            sx[t] = x[n * IN_DIM + t];
        }
        __syncthreads();
        float acc = sb[t];
        #pragma unroll
        for (int kk = 0; kk < IN_DIM; kk++)
            acc += sagg[kk] * sWl[kk * HID + t] + sx[kk] * sWr[kk * HID + t];
        hout[n * HID + t] = fmaxf(acc, 0.f);
        __syncthreads();
    }
}

// ---------------- fused SAGE layer: gather-mean + dual GEMM + relu ----------
#define TK  32
#define SWS 132   // 528 B row stride (16B multiple)
#define AGS 132   // 528 B row stride (16B multiple)
#define SMEM_SAGE ((TK * SWS + 64 * AGS) * 4)   // 50688 B

__global__ void __launch_bounds__(256)
k_sage(const float* __restrict__ hin,
       const float* __restrict__ Wl, const float* __restrict__ Wr,
       const float* __restrict__ b, float* __restrict__ hout) {
    extern __shared__ float sm[];
    float* sW   = sm;             // [TK][SWS]
    float* sAgg = sm + TK * SWS;  // [64][AGS]
    int t = threadIdx.x;
    int nbase = blockIdx.x * 64;

    // ---- phase 1: gather-aggregate (warp w handles rows 8w..8w+7) ----
    {
        int w = t >> 5, lane = t & 31;
        for (int r = 0; r < 8; r++) {
            int row = (w << 3) + r;
            int n = nbase + row;
            float4 s0 = make_float4(0.f, 0.f, 0.f, 0.f);
            float4 s1 = make_float4(0.f, 0.f, 0.f, 0.f);
            if (n < N_NODES) {
                int e0 = g_off[n], e1 = g_off[n + 1];
                int e = e0;
                for (; e + 1 < e1; e += 2) {
                    float4 v0 = *((const float4*)(hin + g_esrc[e]     * HID) + lane);
                    float4 v1 = *((const float4*)(hin + g_esrc[e + 1] * HID) + lane);
                    s0.x += v0.x; s0.y += v0.y; s0.z += v0.z; s0.w += v0.w;
                    s1.x += v1.x; s1.y += v1.y; s1.z += v1.z; s1.w += v1.w;
                }
                if (e < e1) {
                    float4 v0 = *((const float4*)(hin + g_esrc[e] * HID) + lane);
                    s0.x += v0.x; s0.y += v0.y; s0.z += v0.z; s0.w += v0.w;
                }
                float inv = g_invdeg[n];
                s0.x = (s0.x + s1.x) * inv;
                s0.y = (s0.y + s1.y) * inv;
                s0.z = (s0.z + s1.z) * inv;
                s0.w = (s0.w + s1.w) * inv;
            }
            *(float4*)(sAgg + row * AGS + lane * 4) = s0;
        }
    }

    // ---- phase 2: dual GEMM ----
    int row0 = (t >> 4) << 2;   // 0..60 step 4
    int col0 = (t & 15) << 3;   // 0..120 step 8

    ull acc[4][4];
    #pragma unroll
    for (int c = 0; c < 4; c++) {
        ull bv = packf2(b[col0 + 2 * c], b[col0 + 2 * c + 1]);
        #pragma unroll
        for (int r = 0; r < 4; r++) acc[r][c] = bv;
    }

    for (int ch = 0; ch < 8; ch++) {
        const float* Wsrc = (ch < 4) ? Wl : Wr;
        int koff = (ch & 3) * TK;
        __syncthreads();   // previous chunk's reads done (covers gather at ch=0)
        for (int i = t; i < 4096; i += 256) {
            int o = i >> 5, kk = i & 31;
            sW[kk * SWS + o] = Wsrc[o * HID + koff + kk];
        }
        if (ch >= 4) {   // stage self rows into sAgg slice (agg data dead)
            for (int i = t; i < 512; i += 256) {
                int row = i >> 3, q = i & 7;
                int n = nbase + row;
                float4 v = make_float4(0.f, 0.f, 0.f, 0.f);
                if (n < N_NODES)
                    v = *(const float4*)(hin + n * HID + koff + q * 4);
                *(float4*)(sAgg + row * AGS + koff + q * 4) = v;
            }
        }
        __syncthreads();

        #pragma unroll
        for (int kk = 0; kk < TK; kk += 4) {
            float4 a4[4];
            #pragma unroll
            for (int r = 0; r < 4; r++)
                a4[r] = *(const float4*)(sAgg + (row0 + r) * AGS + koff + kk);
            #pragma unroll
            for (int j = 0; j < 4; j++) {
                ulonglong2 wa = *(const ulonglong2*)(sW + (kk + j) * SWS + col0);
                ulonglong2 wb = *(const ulonglong2*)(sW + (kk + j) * SWS + col0 + 4);
                #pragma unroll
                for (int r = 0; r < 4; r++) {
                    float a = (j == 0) ? a4[r].x : (j == 1) ? a4[r].y
                            : (j == 2) ? a4[r].z : a4[r].w;
                    ull a2 = packf2(a, a);
                    ffma2(acc[r][0], wa.x, a2);
                    ffma2(acc[r][1], wa.y, a2);
                    ffma2(acc[r][2], wb.x, a2);
                    ffma2(acc[r][3], wb.y, a2);
                }
            }
        }
    }

    #pragma unroll
    for (int r = 0; r < 4; r++) {
        int n = nbase + row0 + r;
        if (n < N_NODES) {
            float2 v0 = unpackf2(acc[r][0]);
            float2 v1 = unpackf2(acc[r][1]);
            float2 v2 = unpackf2(acc[r][2]);
            float2 v3 = unpackf2(acc[r][3]);
            float4 o1 = make_float4(fmaxf(v0.x, 0.f), fmaxf(v0.y, 0.f),
                                    fmaxf(v1.x, 0.f), fmaxf(v1.y, 0.f));
            float4 o2 = make_float4(fmaxf(v2.x, 0.f), fmaxf(v2.y, 0.f),
                                    fmaxf(v3.x, 0.f), fmaxf(v3.y, 0.f));
            *(float4*)(hout + n * HID + col0) = o1;
            *(float4*)(hout + n * HID + col0 + 4) = o2;
        }
    }
}

// ---------------- head: out = h @ Wh^T + bh (one warp per node) ----------------
__global__ void k_head(const float* __restrict__ hin,
                       const float* __restrict__ Wh,
                       const float* __restrict__ bh,
                       float* __restrict__ out) {
    __shared__ float sWh[OUT_DIM * HID];
    __shared__ float sbh[OUT_DIM];
    int t = threadIdx.x;
    for (int i = t; i < OUT_DIM * HID; i += 128) sWh[i] = Wh[i];
    if (t < OUT_DIM) sbh[t] = bh[t];
    __syncthreads();
    int lane = t & 31;
    int n = blockIdx.x * 4 + (t >> 5);
    if (n >= N_NODES) return;   // whole warp exits together
    float4 hv = *(const float4*)(hin + n * HID + lane * 4);
    float p[OUT_DIM];
    #pragma unroll
    for (int o = 0; o < OUT_DIM; o++) {
        const float* wr = sWh + o * HID + lane * 4;
        p[o] = hv.x * wr[0] + hv.y * wr[1] + hv.z * wr[2] + hv.w * wr[3];
    }
    #pragma unroll
    for (int o = 0; o < OUT_DIM; o++)
        #pragma unroll
        for (int off = 16; off > 0; off >>= 1)
            p[o] += __shfl_down_sync(0xffffffffu, p[o], off);
    if (lane == 0) {
        float4 r = make_float4(p[0] + sbh[0], p[1] + sbh[1],
                               p[2] + sbh[2], p[3] + sbh[3]);
        *(float4*)(out + n * OUT_DIM) = r;
    }
}

// ---------------- launch ----------------
extern "C" void kernel_launch(void* const* d_in, const int* in_sizes, int n_in,
                              void* d_out, int out_size) {
    int ix = -1, ie = -1, iwh = -1, ibh = -1;
    int w1[2] = {-1, -1}; int nw1 = 0;
    int w2[4] = {-1, -1, -1, -1}; int nw2 = 0;
    int bb[3] = {-1, -1, -1}; int nb = 0;
    for (int i = 0; i < n_in; i++) {
        int s = in_sizes[i];
        if      (s == 800000)  ix = i;
        else if (s == 512)     iwh = i;
        else if (s == 4)       ibh = i;
        else if (s == 2048)    { if (nw1 < 2) w1[nw1++] = i; }
        else if (s == 16384)   { if (nw2 < 4) w2[nw2++] = i; }
        else if (s == 128)     { if (nb  < 3) bb[nb++]  = i; }
        else if (s == 1200000 || s == 2400000) ie = i;
    }
    bool ok = (ix >= 0) && (ie >= 0) && (iwh >= 0) && (ibh >= 0) &&
              (nw1 == 2) && (nw2 == 4) && (nb == 3);

    int iwl1, iwr1, iwl2, iwr2, iwl3, iwr3, ib1, ib2, ib3;
    if (ok) {
        iwl1 = w1[0]; iwr1 = w1[1];
        ib1 = bb[0]; ib2 = bb[1]; ib3 = bb[2];
        if (iwh < w2[0]) { iwl2 = w2[0]; iwl3 = w2[1]; iwr2 = w2[2]; iwr3 = w2[3]; }
        else             { iwl2 = w2[0]; iwr2 = w2[1]; iwl3 = w2[2]; iwr3 = w2[3]; }
    } else {
        ix = 0; ie = 1; iwl1 = 2; iwr1 = 3; ib1 = 4; iwl2 = 5; iwr2 = 6; ib2 = 7;
        iwl3 = 8; iwr3 = 9; ib3 = 10; iwh = 11; ibh = 12;
    }

    const float* x   = (const float*)d_in[ix];
    const void*  ei  = d_in[ie];
    const float* Wl1 = (const float*)d_in[iwl1];
    const float* Wr1 = (const float*)d_in[iwr1];
    const float* b1  = (const float*)d_in[ib1];
    const float* Wl2 = (const float*)d_in[iwl2];
    const float* Wr2 = (const float*)d_in[iwr2];
    const float* b2  = (const float*)d_in[ib2];
    const float* Wl3 = (const float*)d_in[iwl3];
    const float* Wr3 = (const float*)d_in[iwr3];
    const float* b3  = (const float*)d_in[ib3];
    const float* Wh  = (const float*)d_in[iwh];
    const float* bh  = (const float*)d_in[ibh];
    float* out = (float*)d_out;

    float *hA = nullptr, *hB = nullptr;
    cudaGetSymbolAddress((void**)&hA, g_hA);
    cudaGetSymbolAddress((void**)&hB, g_hB);

    cudaFuncSetAttribute(k_sage,
                         cudaFuncAttributeMaxDynamicSharedMemorySize, SMEM_SAGE);

    k_detect<<<1, 32>>>((const unsigned int*)ei);            // 0
    k_count<<<(N_EDGES + 255) / 256, 256>>>(ei);             // 1
    k_offsets_all<<<NB, 256>>>();                            // 2 (also zeroes g_cur)
    k_fill<<<(N_EDGES + 255) / 256, 256>>>(ei);              // 3
    k_layer1<<<1184, 128>>>(x, Wl1, Wr1, b1, hA);            // 4 (also zeroes g_deg)
    k_sage<<<NT_GEMM, 256, SMEM_SAGE>>>(hA, Wl2, Wr2, b2, hB);  // 5 <- ncu slot
    k_sage<<<NT_GEMM, 256, SMEM_SAGE>>>(hB, Wl3, Wr3, b3, hA);  // 6
    k_head<<<(N_NODES + 3) / 4, 128>>>(hA, Wh, bh, out);     // 7
}

// round 9
// speedup vs baseline: 1.0491x; 1.0491x over previous
#include <cuda_runtime.h>
#include <stdint.h>

#define N_NODES 50000
#define N_EDGES 600000
#define IN_DIM  16
#define HID     128
#define OUT_DIM 4
#define NT_GEMM ((N_NODES + 63) / 64)   // 782 row-tiles of 64
#define NB      ((N_NODES + 255) / 256) // 196 scan chunks

// ---------------- device scratch (no runtime allocation allowed) ----------------
__device__ int   g_deg[N_NODES];     // zero at start (static init + self-clean in k_layer1)
__device__ int   g_cur[N_NODES];     // zeroed in k_offsets_all each call
__device__ int   g_off[N_NODES + 1];
__device__ int   g_esrc[N_EDGES];
__device__ float g_invdeg[N_NODES];
__device__ float g_hA[N_NODES * HID];
__device__ float g_hB[N_NODES * HID];

// ---------------- f32x2 helpers (Blackwell packed fp32) ----------------
typedef unsigned long long ull;

__device__ __forceinline__ ull packf2(float x, float y) {
    ull r; asm("mov.b64 %0, {%1, %2};" : "=l"(r) : "f"(x), "f"(y)); return r;
}
__device__ __forceinline__ void ffma2(ull& d, ull a, ull b) {
    asm("fma.rn.f32x2 %0, %1, %2, %0;" : "+l"(d) : "l"(a), "l"(b));
}
__device__ __forceinline__ float2 unpackf2(ull v) {
    float2 r; asm("mov.b64 {%0, %1}, %2;" : "=f"(r.x), "=f"(r.y) : "l"(v)); return r;
}

// ---------------- per-block inline dtype detection (int64 vs int32) ----------
// If edge_index is int64 (LE, ids < 2^31), every odd 32-bit word is 0.
// First 64 odd words all-zero for int32 data has ~0 probability.
__device__ __forceinline__ int detect_is64_block(const void* ei, int tid) {
    __shared__ int s_is64;
    if (tid == 0) {
        const unsigned int* p = (const unsigned int*)ei;
        unsigned int acc = 0;
        #pragma unroll
        for (int i = 0; i < 64; i++) acc |= p[2 * i + 1];
        s_is64 = (acc == 0) ? 1 : 0;
    }
    __syncthreads();
    return s_is64;
}

__device__ __forceinline__ int load_edge(const void* ei, int idx, int is64) {
    if (is64) return (int)((const long long*)ei)[idx];
    return ((const int*)ei)[idx];
}

// ---------------- CSR build ----------------
__global__ void k_count(const void* __restrict__ ei) {
    int is64 = detect_is64_block(ei, threadIdx.x);
    int e = blockIdx.x * blockDim.x + threadIdx.x;
    if (e >= N_EDGES) return;
    int d = load_edge(ei, N_EDGES + e, is64);
    if ((unsigned)d < (unsigned)N_NODES)
        atomicAdd(&g_deg[d], 1);
}

// Single-kernel scan: every block (196 x 256) redundantly computes all chunk
// sums + their prefix, then scans its own 256-element chunk. Also writes
// invdeg and zeroes g_cur for the subsequent k_fill.
__global__ void k_offsets_all() {
    __shared__ int cs[256];
    __shared__ int inc[256];
    __shared__ int ws[8];
    int t = threadIdx.x, lane = t & 31, w = t >> 5;

    int s = 0;
    if (t < NB) {
        const int* p = g_deg + t * 256;
        int lim = N_NODES - t * 256; if (lim > 256) lim = 256;
        for (int j = 0; j < lim; j++) s += p[j];
    }
    cs[t] = s;
    __syncthreads();

    {
        int x = cs[t];
        #pragma unroll
        for (int d = 1; d < 32; d <<= 1) {
            int y = __shfl_up_sync(0xffffffffu, x, d);
            if (lane >= d) x += y;
        }
        if (lane == 31) ws[w] = x;
        __syncthreads();
        if (t < 8) {
            int sv = ws[t], xs = sv;
            #pragma unroll
            for (int d = 1; d < 8; d <<= 1) {
                int y = __shfl_up_sync(0x000000ffu, xs, d);
                if (t >= d) xs += y;
            }
            ws[t] = xs - sv;
        }
        __syncthreads();
        inc[t] = ws[w] + x;
        __syncthreads();
    }
    int base  = inc[blockIdx.x] - cs[blockIdx.x];
    int total = inc[255];
    __syncthreads();

    int i = blockIdx.x * 256 + t;
    int v = (i < N_NODES) ? g_deg[i] : 0;
    int x = v;
    #pragma unroll
    for (int d = 1; d < 32; d <<= 1) {
        int y = __shfl_up_sync(0xffffffffu, x, d);
        if (lane >= d) x += y;
    }
    if (lane == 31) ws[w] = x;
    __syncthreads();
    if (t < 8) {
        int sv = ws[t], xs = sv;
        #pragma unroll
        for (int d = 1; d < 8; d <<= 1) {
            int y = __shfl_up_sync(0x000000ffu, xs, d);
            if (t >= d) xs += y;
        }
        ws[t] = xs - sv;
    }
    __syncthreads();
    if (i < N_NODES) {
        g_off[i]    = base + ws[w] + (x - v);
        g_invdeg[i] = 1.0f / (float)(v > 0 ? v : 1);
        g_cur[i]    = 0;
    }
    if (blockIdx.x == NB - 1 && t == 0) g_off[N_NODES] = total;
}

__global__ void k_fill(const void* __restrict__ ei) {
    int is64 = detect_is64_block(ei, threadIdx.x);
    int e = blockIdx.x * blockDim.x + threadIdx.x;
    if (e >= N_EDGES) return;
    int d = load_edge(ei, N_EDGES + e, is64);
    if ((unsigned)d >= (unsigned)N_NODES) return;
    int s = load_edge(ei, e, is64);
    if ((unsigned)s >= (unsigned)N_NODES) s = 0;
    int p = g_off[d] + atomicAdd(&g_cur[d], 1);
    if ((unsigned)p < (unsigned)N_EDGES)
        g_esrc[p] = s;
}

// ---------------- layer 1: warp-per-node, shfl-based, no per-node syncs ----
// out = relu(mean_nbr(x) @ Wl^T + x @ Wr^T + b). Also self-cleans g_deg.
__global__ void __launch_bounds__(256)
k_layer1(const float* __restrict__ x,
         const float* __restrict__ Wl,
         const float* __restrict__ Wr,
         const float* __restrict__ b,
         float* __restrict__ hout) {
    for (int i = blockIdx.x * blockDim.x + threadIdx.x; i < N_NODES;
         i += gridDim.x * blockDim.x)
        g_deg[i] = 0;

    __shared__ float sWl[IN_DIM * HID], sWr[IN_DIM * HID], sb[HID];
    int t = threadIdx.x;
    for (int i = t; i < IN_DIM * HID; i += 256) {
        int o = i >> 4, k = i & 15;
        sWl[k * HID + o] = Wl[i];   // sW[k][o] = W[o][k]
        sWr[k * HID + o] = Wr[i];
    }
    for (int i = t; i < HID; i += 256) sb[i] = b[i];
    __syncthreads();

    int lane = t & 31, w = t >> 5;
    int k = lane & 15, j = lane >> 4;   // feature k, edge slot j in {0,1}
    for (int n = blockIdx.x * 8 + w; n < N_NODES; n += gridDim.x * 8) {
        int e0 = g_off[n], e1 = g_off[n + 1];
        float s = 0.f;
        int e = e0 + j;
        for (; e + 2 < e1; e += 4) {   // 2 independent loads in flight per lane
            int s0 = g_esrc[e], s1 = g_esrc[e + 2];
            s += x[s0 * IN_DIM + k] + x[s1 * IN_DIM + k];
        }
        if (e < e1) s += x[g_esrc[e] * IN_DIM + k];
        s += __shfl_down_sync(0xffffffffu, s, 16);   // fold slot 1 into slot 0
        float a  = s * g_invdeg[n];                  // valid in lanes 0-15
        float xs = (lane < 16) ? x[n * IN_DIM + lane] : 0.f;

        float4 acc = *(const float4*)(sb + lane * 4);
        #pragma unroll
        for (int kk = 0; kk < IN_DIM; kk++) {
            float ak = __shfl_sync(0xffffffffu, a,  kk);
            float xk = __shfl_sync(0xffffffffu, xs, kk);
            float4 wl = *(const float4*)(sWl + kk * HID + lane * 4);
            float4 wr = *(const float4*)(sWr + kk * HID + lane * 4);
            acc.x += ak * wl.x + xk * wr.x;
            acc.y += ak * wl.y + xk * wr.y;
            acc.z += ak * wl.z + xk * wr.z;
            acc.w += ak * wl.w + xk * wr.w;
        }
        acc.x = fmaxf(acc.x, 0.f); acc.y = fmaxf(acc.y, 0.f);
        acc.z = fmaxf(acc.z, 0.f); acc.w = fmaxf(acc.w, 0.f);
        *(float4*)(hout + n * HID + lane * 4) = acc;
    }
}

// ---------------- fused SAGE layer: gather-mean + dual GEMM + relu ----------
#define TK  32
#define SWS 132   // 528 B row stride (16B multiple)
#define AGS 132   // 528 B row stride (16B multiple)
#define SMEM_SAGE ((TK * SWS + 64 * AGS) * 4)   // 50688 B

__global__ void __launch_bounds__(256)
k_sage(const float* __restrict__ hin,
       const float* __restrict__ Wl, const float* __restrict__ Wr,
       const float* __restrict__ b, float* __restrict__ hout) {
    extern __shared__ float sm[];
    float* sW   = sm;             // [TK][SWS]
    float* sAgg = sm + TK * SWS;  // [64][AGS]
    int t = threadIdx.x;
    int nbase = blockIdx.x * 64;

    // ---- phase 1: gather-aggregate, 4-edge unroll (MLP=4 per warp) ----
    {
        int w = t >> 5, lane = t & 31;
        for (int r = 0; r < 8; r++) {
            int row = (w << 3) + r;
            int n = nbase + row;
            float4 a0 = make_float4(0.f, 0.f, 0.f, 0.f);
            float4 a1 = make_float4(0.f, 0.f, 0.f, 0.f);
            if (n < N_NODES) {
                int e0 = g_off[n], e1 = g_off[n + 1];
                int e = e0;
                for (; e + 3 < e1; e += 4) {
                    int s0 = g_esrc[e],     s1 = g_esrc[e + 1];
                    int s2 = g_esrc[e + 2], s3 = g_esrc[e + 3];
                    float4 v0 = ((const float4*)(hin + s0 * HID))[lane];
                    float4 v1 = ((const float4*)(hin + s1 * HID))[lane];
                    float4 v2 = ((const float4*)(hin + s2 * HID))[lane];
                    float4 v3 = ((const float4*)(hin + s3 * HID))[lane];
                    a0.x += v0.x + v1.x; a0.y += v0.y + v1.y;
                    a0.z += v0.z + v1.z; a0.w += v0.w + v1.w;
                    a1.x += v2.x + v3.x; a1.y += v2.y + v3.y;
                    a1.z += v2.z + v3.z; a1.w += v2.w + v3.w;
                }
                for (; e < e1; e++) {
                    float4 v0 = ((const float4*)(hin + g_esrc[e] * HID))[lane];
                    a0.x += v0.x; a0.y += v0.y; a0.z += v0.z; a0.w += v0.w;
                }
                float inv = g_invdeg[n];
                a0.x = (a0.x + a1.x) * inv;
                a0.y = (a0.y + a1.y) * inv;
                a0.z = (a0.z + a1.z) * inv;
                a0.w = (a0.w + a1.w) * inv;
            }
            *(float4*)(sAgg + row * AGS + lane * 4) = a0;
        }
    }

    // ---- phase 2: dual GEMM (f32x2) ----
    int row0 = (t >> 4) << 2;   // 0..60 step 4
    int col0 = (t & 15) << 3;   // 0..120 step 8

    ull acc[4][4];
    #pragma unroll
    for (int c = 0; c < 4; c++) {
        ull bv = packf2(b[col0 + 2 * c], b[col0 + 2 * c + 1]);
        #pragma unroll
        for (int r = 0; r < 4; r++) acc[r][c] = bv;
    }

    for (int ch = 0; ch < 8; ch++) {
        const float* Wsrc = (ch < 4) ? Wl : Wr;
        int koff = (ch & 3) * TK;
        __syncthreads();   // previous chunk's reads done (covers gather at ch=0)
        for (int i = t; i < 4096; i += 256) {
            int o = i >> 5, kk = i & 31;
            sW[kk * SWS + o] = Wsrc[o * HID + koff + kk];
        }
        if (ch >= 4) {   // stage self rows into sAgg slice (agg data dead)
            for (int i = t; i < 512; i += 256) {
                int row = i >> 3, q = i & 7;
                int n = nbase + row;
                float4 v = make_float4(0.f, 0.f, 0.f, 0.f);
                if (n < N_NODES)
                    v = *(const float4*)(hin + n * HID + koff + q * 4);
                *(float4*)(sAgg + row * AGS + koff + q * 4) = v;
            }
        }
        __syncthreads();

        #pragma unroll
        for (int kk = 0; kk < TK; kk += 4) {
            float4 a4[4];
            #pragma unroll
            for (int r = 0; r < 4; r++)
                a4[r] = *(const float4*)(sAgg + (row0 + r) * AGS + koff + kk);
            #pragma unroll
            for (int j = 0; j < 4; j++) {
                ulonglong2 wa = *(const ulonglong2*)(sW + (kk + j) * SWS + col0);
                ulonglong2 wb = *(const ulonglong2*)(sW + (kk + j) * SWS + col0 + 4);
                #pragma unroll
                for (int r = 0; r < 4; r++) {
                    float a = (j == 0) ? a4[r].x : (j == 1) ? a4[r].y
                            : (j == 2) ? a4[r].z : a4[r].w;
                    ull a2 = packf2(a, a);
                    ffma2(acc[r][0], wa.x, a2);
                    ffma2(acc[r][1], wa.y, a2);
                    ffma2(acc[r][2], wb.x, a2);
                    ffma2(acc[r][3], wb.y, a2);
                }
            }
        }
    }

    #pragma unroll
    for (int r = 0; r < 4; r++) {
        int n = nbase + row0 + r;
        if (n < N_NODES) {
            float2 v0 = unpackf2(acc[r][0]);
            float2 v1 = unpackf2(acc[r][1]);
            float2 v2 = unpackf2(acc[r][2]);
            float2 v3 = unpackf2(acc[r][3]);
            float4 o1 = make_float4(fmaxf(v0.x, 0.f), fmaxf(v0.y, 0.f),
                                    fmaxf(v1.x, 0.f), fmaxf(v1.y, 0.f));
            float4 o2 = make_float4(fmaxf(v2.x, 0.f), fmaxf(v2.y, 0.f),
                                    fmaxf(v3.x, 0.f), fmaxf(v3.y, 0.f));
            *(float4*)(hout + n * HID + col0) = o1;
            *(float4*)(hout + n * HID + col0 + 4) = o2;
        }
    }
}

// ---------------- head: out = h @ Wh^T + bh (one warp per node) ----------------
__global__ void k_head(const float* __restrict__ hin,
                       const float* __restrict__ Wh,
                       const float* __restrict__ bh,
                       float* __restrict__ out) {
    __shared__ float sWh[OUT_DIM * HID];
    __shared__ float sbh[OUT_DIM];
    int t = threadIdx.x;
    for (int i = t; i < OUT_DIM * HID; i += 128) sWh[i] = Wh[i];
    if (t < OUT_DIM) sbh[t] = bh[t];
    __syncthreads();
    int lane = t & 31;
    int n = blockIdx.x * 4 + (t >> 5);
    if (n >= N_NODES) return;   // whole warp exits together
    float4 hv = *(const float4*)(hin + n * HID + lane * 4);
    float p[OUT_DIM];
    #pragma unroll
    for (int o = 0; o < OUT_DIM; o++) {
        const float* wr = sWh + o * HID + lane * 4;
        p[o] = hv.x * wr[0] + hv.y * wr[1] + hv.z * wr[2] + hv.w * wr[3];
    }
    #pragma unroll
    for (int o = 0; o < OUT_DIM; o++)
        #pragma unroll
        for (int off = 16; off > 0; off >>= 1)
            p[o] += __shfl_down_sync(0xffffffffu, p[o], off);
    if (lane == 0) {
        float4 r = make_float4(p[0] + sbh[0], p[1] + sbh[1],
                               p[2] + sbh[2], p[3] + sbh[3]);
        *(float4*)(out + n * OUT_DIM) = r;
    }
}

// ---------------- launch ----------------
extern "C" void kernel_launch(void* const* d_in, const int* in_sizes, int n_in,
                              void* d_out, int out_size) {
    int ix = -1, ie = -1, iwh = -1, ibh = -1;
    int w1[2] = {-1, -1}; int nw1 = 0;
    int w2[4] = {-1, -1, -1, -1}; int nw2 = 0;
    int bb[3] = {-1, -1, -1}; int nb = 0;
    for (int i = 0; i < n_in; i++) {
        int s = in_sizes[i];
        if      (s == 800000)  ix = i;
        else if (s == 512)     iwh = i;
        else if (s == 4)       ibh = i;
        else if (s == 2048)    { if (nw1 < 2) w1[nw1++] = i; }
        else if (s == 16384)   { if (nw2 < 4) w2[nw2++] = i; }
        else if (s == 128)     { if (nb  < 3) bb[nb++]  = i; }
        else if (s == 1200000 || s == 2400000) ie = i;
    }
    bool ok = (ix >= 0) && (ie >= 0) && (iwh >= 0) && (ibh >= 0) &&
              (nw1 == 2) && (nw2 == 4) && (nb == 3);

    int iwl1, iwr1, iwl2, iwr2, iwl3, iwr3, ib1, ib2, ib3;
    if (ok) {
        iwl1 = w1[0]; iwr1 = w1[1];
        ib1 = bb[0]; ib2 = bb[1]; ib3 = bb[2];
        if (iwh < w2[0]) { iwl2 = w2[0]; iwl3 = w2[1]; iwr2 = w2[2]; iwr3 = w2[3]; }
        else             { iwl2 = w2[0]; iwr2 = w2[1]; iwl3 = w2[2]; iwr3 = w2[3]; }
    } else {
        ix = 0; ie = 1; iwl1 = 2; iwr1 = 3; ib1 = 4; iwl2 = 5; iwr2 = 6; ib2 = 7;
        iwl3 = 8; iwr3 = 9; ib3 = 10; iwh = 11; ibh = 12;
    }

    const float* x   = (const float*)d_in[ix];
    const void*  ei  = d_in[ie];
    const float* Wl1 = (const float*)d_in[iwl1];
    const float* Wr1 = (const float*)d_in[iwr1];
    const float* b1  = (const float*)d_in[ib1];
    const float* Wl2 = (const float*)d_in[iwl2];
    const float* Wr2 = (const float*)d_in[iwr2];
    const float* b2  = (const float*)d_in[ib2];
    const float* Wl3 = (const float*)d_in[iwl3];
    const float* Wr3 = (const float*)d_in[iwr3];
    const float* b3  = (const float*)d_in[ib3];
    const float* Wh  = (const float*)d_in[iwh];
    const float* bh  = (const float*)d_in[ibh];
    float* out = (float*)d_out;

    float *hA = nullptr, *hB = nullptr;
    cudaGetSymbolAddress((void**)&hA, g_hA);
    cudaGetSymbolAddress((void**)&hB, g_hB);

    cudaFuncSetAttribute(k_sage,
                         cudaFuncAttributeMaxDynamicSharedMemorySize, SMEM_SAGE);

    k_count<<<(N_EDGES + 255) / 256, 256>>>(ei);                // 0
    k_offsets_all<<<NB, 256>>>();                               // 1
    k_fill<<<(N_EDGES + 255) / 256, 256>>>(ei);                 // 2
    k_layer1<<<1184, 256>>>(x, Wl1, Wr1, b1, hA);               // 3 <- ncu slot
    k_sage<<<NT_GEMM, 256, SMEM_SAGE>>>(hA, Wl2, Wr2, b2, hB);  // 4
    k_sage<<<NT_GEMM, 256, SMEM_SAGE>>>(hB, Wl3, Wr3, b3, hA);  // 5
    k_head<<<(N_NODES + 3) / 4, 128>>>(hA, Wh, bh, out);        // 6
}